// round 1
// baseline (speedup 1.0000x reference)
#include <cuda_runtime.h>
#include <math.h>

#define NND 50000
#define NED 800000
#define D   64

// Scratch (allocation-free: device globals)
__device__ float g_h1[NND * D];    // feat * out_norm
__device__ float g_agg1[NND * D];  // layer-1 scatter accumulator
__device__ float g_h2[NND * D];    // relu(agg1*inn @ W1 + b1) * out_norm
__device__ float g_agg2[NND * D];  // layer-2 scatter accumulator
__device__ int   g_degout[NND];
__device__ int   g_degin[NND];
__device__ float g_outn[NND];
__device__ float g_inn[NND];

// ---------------------------------------------------------------- zero scratch
__global__ void k_zero(int nN) {
    int tid = blockIdx.x * blockDim.x + threadIdx.x;
    int total4 = nN * (D / 4);
    float4 z = make_float4(0.f, 0.f, 0.f, 0.f);
    if (tid < total4) {
        reinterpret_cast<float4*>(g_agg1)[tid] = z;
        reinterpret_cast<float4*>(g_agg2)[tid] = z;
    }
    if (tid < nN) { g_degout[tid] = 0; g_degin[tid] = 0; }
}

// ---------------------------------------------------------------- degrees
__global__ void k_deg(const int* __restrict__ src, const int* __restrict__ dst, int nE) {
    int e = blockIdx.x * blockDim.x + threadIdx.x;
    if (e < nE) {
        atomicAdd(&g_degout[src[e]], 1);
        atomicAdd(&g_degin[dst[e]], 1);
    }
}

// ---------------------------------------------------------------- norms
__global__ void k_norm(int nN) {
    int i = blockIdx.x * blockDim.x + threadIdx.x;
    if (i < nN) {
        g_outn[i] = rsqrtf(fmaxf((float)g_degout[i], 1.f));
        g_inn[i]  = rsqrtf(fmaxf((float)g_degin[i], 1.f));
    }
}

// ---------------------------------------------------------------- h1 = feat * out_norm
__global__ void k_scale(const float4* __restrict__ feat4, int nN) {
    int tid = blockIdx.x * blockDim.x + threadIdx.x;
    if (tid < nN * (D / 4)) {
        int node = tid >> 4;
        float s = g_outn[node];
        float4 v = feat4[tid];
        v.x *= s; v.y *= s; v.z *= s; v.w *= s;
        reinterpret_cast<float4*>(g_h1)[tid] = v;
    }
}

// ---------------------------------------------------------------- edge scatter
// 16 threads per edge, one float4 chunk each; vector red into L2-resident agg.
template <int LAYER>
__global__ void k_edge(const int* __restrict__ src, const int* __restrict__ dst, int nE) {
    int tid = blockIdx.x * blockDim.x + threadIdx.x;
    if (tid >= nE * (D / 4)) return;
    int e = tid >> 4;
    int c = tid & 15;
    int s = src[e];
    int d = dst[e];
    const float4* h = (LAYER == 0) ? reinterpret_cast<const float4*>(g_h1)
                                   : reinterpret_cast<const float4*>(g_h2);
    float* agg = (LAYER == 0) ? g_agg1 : g_agg2;
    float4 v = h[s * 16 + c];
    float* p = agg + (size_t)d * D + c * 4;
    asm volatile("red.global.add.v4.f32 [%0], {%1, %2, %3, %4};"
                 :: "l"(p), "f"(v.x), "f"(v.y), "f"(v.z), "f"(v.w)
                 : "memory");
}

// ---------------------------------------------------------------- layer-1 MLP
// h2 = relu((agg1 * in_norm) @ W1 + b1) * out_norm   (one warp per node)
__global__ void k_mlp1(const float* __restrict__ W1, const float* __restrict__ b1, int nN) {
    __shared__ float Ws[D * D];
    __shared__ float bs[D];
    int t = threadIdx.x;
    for (int i = t; i < D * D; i += blockDim.x) Ws[i] = W1[i];
    if (t < D) bs[t] = b1[t];
    __syncthreads();

    int lane = t & 31;
    int wid = t >> 5;
    int warps = (blockDim.x >> 5) * gridDim.x;
    for (int node = blockIdx.x * (blockDim.x >> 5) + wid; node < nN; node += warps) {
        float inn = g_inn[node];
        float outn = g_outn[node];
        float x0 = g_agg1[node * D + lane] * inn;
        float x1 = g_agg1[node * D + 32 + lane] * inn;
        float a0 = bs[lane];
        float a1 = bs[lane + 32];
#pragma unroll
        for (int k = 0; k < D; k++) {
            float v = __shfl_sync(0xffffffffu, (k < 32) ? x0 : x1, k & 31);
            a0 += v * Ws[k * D + lane];
            a1 += v * Ws[k * D + lane + 32];
        }
        a0 = fmaxf(a0, 0.f) * outn;
        a1 = fmaxf(a1, 0.f) * outn;
        g_h2[node * D + lane] = a0;
        g_h2[node * D + 32 + lane] = a1;
    }
}

// ---------------------------------------------------------------- output layer
// out = sigmoid((agg2 * in_norm) @ W2 + b2)   (one warp per node)
__global__ void k_out(const float* __restrict__ W2, const float* __restrict__ b2,
                      float* __restrict__ out, int nN) {
    int lane = threadIdx.x & 31;
    int wid = threadIdx.x >> 5;
    int warps = (blockDim.x >> 5) * gridDim.x;
    float w0 = W2[lane];
    float w1 = W2[lane + 32];
    float bb = b2[0];
    for (int node = blockIdx.x * (blockDim.x >> 5) + wid; node < nN; node += warps) {
        float inn = g_inn[node];
        float acc = g_agg2[node * D + lane] * w0 + g_agg2[node * D + 32 + lane] * w1;
        acc *= inn;
#pragma unroll
        for (int o = 16; o; o >>= 1) acc += __shfl_xor_sync(0xffffffffu, acc, o);
        if (lane == 0) out[node] = 1.f / (1.f + expf(-(acc + bb)));
    }
}

// ---------------------------------------------------------------- launch
extern "C" void kernel_launch(void* const* d_in, const int* in_sizes, int n_in,
                              void* d_out, int out_size) {
    const float* feat = (const float*)d_in[0];
    const float* W1   = (const float*)d_in[1];
    const float* b1   = (const float*)d_in[2];
    const float* W2   = (const float*)d_in[3];
    const float* b2   = (const float*)d_in[4];
    const int*   src  = (const int*)d_in[5];
    const int*   dst  = (const int*)d_in[6];
    float* out = (float*)d_out;

    int nN = in_sizes[0] / D;
    int nE = in_sizes[5];

    const int B = 256;
    int gZero  = (nN * (D / 4) + B - 1) / B;
    int gDeg   = (nE + B - 1) / B;
    int gNode  = (nN + B - 1) / B;
    int gEdge  = (nE * (D / 4) + B - 1) / B;
    int gWarp  = (nN / (B / 32) + 1);

    k_zero <<<gZero, B>>>(nN);
    k_deg  <<<gDeg,  B>>>(src, dst, nE);
    k_norm <<<gNode, B>>>(nN);
    k_scale<<<gZero, B>>>(reinterpret_cast<const float4*>(feat), nN);
    k_edge<0><<<gEdge, B>>>(src, dst, nE);
    k_mlp1 <<<gWarp, B>>>(W1, b1, nN);
    k_edge<1><<<gEdge, B>>>(src, dst, nE);
    k_out  <<<gWarp, B>>>(W2, b2, out, nN);
}

// round 2
// speedup vs baseline: 1.3093x; 1.3093x over previous
#include <cuda_runtime.h>
#include <math.h>

#define NND 50000
#define NED 800000
#define D   64
#define SB  256
#define NSB_MAX 256   // supports up to 65536 nodes

// ---- scratch (allocation-free device globals) ----
__device__ int   g_degout[NND];
__device__ int   g_degin[NND];
__device__ float g_outn[NND];
__device__ float g_inn[NND];
__device__ int   g_rowstart[NND];
__device__ int   g_cursor[NND];
__device__ int   g_esrc[NED];       // edge src ids grouped by dst (CSR)
__device__ float g_h2[NND * D];     // layer-1 output (out_norm applied)
__device__ int   g_partial[NSB_MAX];

// ---------------------------------------------------------------- zero degrees
__global__ void k_init(int nN) {
    int i = blockIdx.x * blockDim.x + threadIdx.x;
    if (i < nN) { g_degout[i] = 0; g_degin[i] = 0; }
}

// ---------------------------------------------------------------- degrees (REDG)
__global__ void k_deg(const int* __restrict__ src, const int* __restrict__ dst, int nE) {
    int e = blockIdx.x * blockDim.x + threadIdx.x;
    if (e < nE) {
        atomicAdd(&g_degout[src[e]], 1);
        atomicAdd(&g_degin[dst[e]], 1);
    }
}

// ---------------------------------------------------------------- scan pass 1: block sums of degin
__global__ void k_scan1(int nN) {
    __shared__ int s[SB];
    int i = blockIdx.x * SB + threadIdx.x;
    int v = (i < nN) ? g_degin[i] : 0;
    s[threadIdx.x] = v;
    __syncthreads();
    for (int off = SB / 2; off > 0; off >>= 1) {
        if (threadIdx.x < off) s[threadIdx.x] += s[threadIdx.x + off];
        __syncthreads();
    }
    if (threadIdx.x == 0) g_partial[blockIdx.x] = s[0];
}

// ---------------------------------------------------------------- scan pass 2: exclusive scan of block sums (1 block)
__global__ void k_scan2(int nBlocks) {
    __shared__ int s[NSB_MAX];
    int t = threadIdx.x;
    int v = (t < nBlocks) ? g_partial[t] : 0;
    s[t] = v;
    __syncthreads();
    for (int off = 1; off < NSB_MAX; off <<= 1) {
        int u = (t >= off) ? s[t - off] : 0;
        __syncthreads();
        s[t] += u;
        __syncthreads();
    }
    if (t < nBlocks) g_partial[t] = s[t] - v;   // exclusive
}

// ---------------------------------------------------------------- scan pass 3: rowstart, cursors, norms
__global__ void k_scan3(int nN) {
    __shared__ int s[SB];
    int i = blockIdx.x * SB + threadIdx.x;
    int t = threadIdx.x;
    int deg_in = (i < nN) ? g_degin[i] : 0;
    s[t] = deg_in;
    __syncthreads();
    for (int off = 1; off < SB; off <<= 1) {
        int u = (t >= off) ? s[t - off] : 0;
        __syncthreads();
        s[t] += u;
        __syncthreads();
    }
    if (i < nN) {
        int rs = g_partial[blockIdx.x] + s[t] - deg_in;   // exclusive within block + base
        g_rowstart[i] = rs;
        g_cursor[i]   = rs;
        g_outn[i] = rsqrtf(fmaxf((float)g_degout[i], 1.f));
        g_inn[i]  = rsqrtf(fmaxf((float)deg_in, 1.f));
    }
}

// ---------------------------------------------------------------- CSR fill
__global__ void k_csr(const int* __restrict__ src, const int* __restrict__ dst, int nE) {
    int e = blockIdx.x * blockDim.x + threadIdx.x;
    if (e < nE) {
        int pos = atomicAdd(&g_cursor[dst[e]], 1);
        g_esrc[pos] = src[e];
    }
}

// ---------------------------------------------------------------- layer 1: pull + inn + MLP(relu) + outn -> h2
// one warp per dst node; lane owns dims {lane, lane+32}
__global__ void k_pull1(const float* __restrict__ feat,
                        const float* __restrict__ W1, const float* __restrict__ b1, int nN) {
    __shared__ float Ws[D * D];
    __shared__ float bs[D];
    int t = threadIdx.x;
    for (int i = t; i < D * D; i += blockDim.x) Ws[i] = W1[i];
    if (t < D) bs[t] = b1[t];
    __syncthreads();

    int lane = t & 31;
    int wid  = t >> 5;
    int warps = (blockDim.x >> 5) * gridDim.x;
    for (int node = blockIdx.x * (blockDim.x >> 5) + wid; node < nN; node += warps) {
        int row = g_rowstart[node];
        int deg = g_degin[node];
        float a0 = 0.f, a1 = 0.f;
        for (int base = 0; base < deg; base += 32) {
            int n = min(32, deg - base);
            int eid = (lane < n) ? g_esrc[row + base + lane] : 0;
            for (int j = 0; j < n; j++) {
                int s = __shfl_sync(0xffffffffu, eid, j);
                float os = g_outn[s];
                a0 = fmaf(feat[s * D + lane],      os, a0);
                a1 = fmaf(feat[s * D + 32 + lane], os, a1);
            }
        }
        float inn = g_inn[node];
        float x0 = a0 * inn, x1 = a1 * inn;
        float o0 = bs[lane], o1 = bs[lane + 32];
#pragma unroll
        for (int k = 0; k < D; k++) {
            float v = __shfl_sync(0xffffffffu, (k < 32) ? x0 : x1, k & 31);
            o0 = fmaf(v, Ws[k * D + lane],      o0);
            o1 = fmaf(v, Ws[k * D + lane + 32], o1);
        }
        float on = g_outn[node];
        g_h2[node * D + lane]      = fmaxf(o0, 0.f) * on;
        g_h2[node * D + 32 + lane] = fmaxf(o1, 0.f) * on;
    }
}

// ---------------------------------------------------------------- layer 2: pull + inn + dot(W2)+b2 + sigmoid -> out
__global__ void k_pull2(const float* __restrict__ W2, const float* __restrict__ b2,
                        float* __restrict__ out, int nN) {
    int lane = threadIdx.x & 31;
    int wid  = threadIdx.x >> 5;
    int warps = (blockDim.x >> 5) * gridDim.x;
    float w0 = W2[lane];
    float w1 = W2[lane + 32];
    float bb = b2[0];
    for (int node = blockIdx.x * (blockDim.x >> 5) + wid; node < nN; node += warps) {
        int row = g_rowstart[node];
        int deg = g_degin[node];
        float a0 = 0.f, a1 = 0.f;
        for (int base = 0; base < deg; base += 32) {
            int n = min(32, deg - base);
            int eid = (lane < n) ? g_esrc[row + base + lane] : 0;
            for (int j = 0; j < n; j++) {
                int s = __shfl_sync(0xffffffffu, eid, j);
                a0 += g_h2[s * D + lane];
                a1 += g_h2[s * D + 32 + lane];
            }
        }
        float acc = (a0 * w0 + a1 * w1) * g_inn[node];
#pragma unroll
        for (int o = 16; o; o >>= 1) acc += __shfl_xor_sync(0xffffffffu, acc, o);
        if (lane == 0) out[node] = 1.f / (1.f + expf(-(acc + bb)));
    }
}

// ---------------------------------------------------------------- launch
extern "C" void kernel_launch(void* const* d_in, const int* in_sizes, int n_in,
                              void* d_out, int out_size) {
    const float* feat = (const float*)d_in[0];
    const float* W1   = (const float*)d_in[1];
    const float* b1   = (const float*)d_in[2];
    const float* W2   = (const float*)d_in[3];
    const float* b2   = (const float*)d_in[4];
    const int*   src  = (const int*)d_in[5];
    const int*   dst  = (const int*)d_in[6];
    float* out = (float*)d_out;

    int nN = in_sizes[0] / D;
    int nE = in_sizes[5];

    const int B = 256;
    int gNode   = (nN + B - 1) / B;       // == scan block count
    int gEdge   = (nE + B - 1) / B;
    int gWarp   = (nN + (B / 32) - 1) / (B / 32);

    k_init <<<gNode, B>>>(nN);
    k_deg  <<<gEdge, B>>>(src, dst, nE);
    k_scan1<<<gNode, B>>>(nN);
    k_scan2<<<1, NSB_MAX>>>(gNode);
    k_scan3<<<gNode, B>>>(nN);
    k_csr  <<<gEdge, B>>>(src, dst, nE);
    k_pull1<<<gWarp, B>>>(feat, W1, b1, nN);
    k_pull2<<<gWarp, B>>>(W2, b2, out, nN);
}

// round 3
// speedup vs baseline: 1.5368x; 1.1738x over previous
#include <cuda_runtime.h>
#include <math.h>

#define NND 50000
#define NED 800000
#define D   64

// ---- scratch (allocation-free device globals) ----
__device__ int   g_degout[NND];
__device__ int   g_degin[NND];
__device__ float g_outn[NND];
__device__ float g_inn[NND];
__device__ int   g_rowstart[NND];
__device__ int   g_cursor[NND];
__device__ int   g_esrc[NED];      // edge src ids grouped by dst
__device__ float g_y[NND * D];     // (feat @ W1) * outn
__device__ float g_z[NND];         // outn * dot(relu-layer output, W2)
__device__ int   g_total;

// ---------------------------------------------------------------- init
__global__ void k_init(int nN) {
    int i = blockIdx.x * blockDim.x + threadIdx.x;
    if (i < nN) { g_degout[i] = 0; g_degin[i] = 0; }
    if (i == 0) g_total = 0;
}

// ---------------------------------------------------------------- degrees
__global__ void k_deg(const int* __restrict__ src, const int* __restrict__ dst, int nE) {
    int e = blockIdx.x * blockDim.x + threadIdx.x;
    if (e < nE) {
        atomicAdd(&g_degout[src[e]], 1);
        atomicAdd(&g_degin[dst[e]], 1);
    }
}

// ---------------------------------------------------------------- norms + row offsets (no scan: atomic chunk grab)
__global__ void k_norm(int nN) {
    int i = blockIdx.x * blockDim.x + threadIdx.x;
    if (i < nN) {
        int din = g_degin[i];
        int rs = atomicAdd(&g_total, din);
        g_rowstart[i] = rs;
        g_cursor[i]   = rs;
        g_outn[i] = rsqrtf(fmaxf((float)g_degout[i], 1.f));
        g_inn[i]  = rsqrtf(fmaxf((float)din, 1.f));
    }
}

// ---------------------------------------------------------------- CSR fill
__global__ void k_csr(const int* __restrict__ src, const int* __restrict__ dst, int nE) {
    int e = blockIdx.x * blockDim.x + threadIdx.x;
    if (e < nE) {
        int pos = atomicAdd(&g_cursor[dst[e]], 1);
        g_esrc[pos] = src[e];
    }
}

// ---------------------------------------------------------------- y = (feat @ W1) * outn   (warp per node)
// lane owns output dims {2*lane, 2*lane+1}
__global__ void k_gemm(const float* __restrict__ feat, const float* __restrict__ W1, int nN) {
    __shared__ float2 Ws[D * 32];   // Ws[k*32+lane] = (W1[k][2l], W1[k][2l+1])
    int t = threadIdx.x;
    for (int i = t; i < D * 32; i += blockDim.x)
        Ws[i] = reinterpret_cast<const float2*>(W1)[i];
    __syncthreads();

    int lane = t & 31;
    int wid  = t >> 5;
    int warps = (blockDim.x >> 5) * gridDim.x;
    for (int node = blockIdx.x * (blockDim.x >> 5) + wid; node < nN; node += warps) {
        float x0 = feat[node * D + lane];
        float x1 = feat[node * D + 32 + lane];
        float ax = 0.f, ay = 0.f;
#pragma unroll
        for (int k = 0; k < D; k++) {
            float v = __shfl_sync(0xffffffffu, (k < 32) ? x0 : x1, k & 31);
            float2 w = Ws[k * 32 + lane];
            ax = fmaf(v, w.x, ax);
            ay = fmaf(v, w.y, ay);
        }
        float on = g_outn[node];
        float2 r; r.x = ax * on; r.y = ay * on;
        reinterpret_cast<float2*>(g_y)[node * 32 + lane] = r;
    }
}

// ---------------------------------------------------------------- layer 1 pull + epilogue -> z
// z[node] = outn[node] * dot( relu(inn*Σ y[src] + b1), W2 )
__global__ void k_pull1(const float* __restrict__ b1, const float* __restrict__ W2, int nN) {
    int t = threadIdx.x;
    int lane = t & 31;
    int wid  = t >> 5;
    int warps = (blockDim.x >> 5) * gridDim.x;
    float2 b1v = reinterpret_cast<const float2*>(b1)[lane];
    float2 w2v = reinterpret_cast<const float2*>(W2)[lane];
    const float2* y2 = reinterpret_cast<const float2*>(g_y);

    for (int node = blockIdx.x * (blockDim.x >> 5) + wid; node < nN; node += warps) {
        int row = g_rowstart[node];
        int deg = g_degin[node];
        float ax = 0.f, ay = 0.f;
        for (int base = 0; base < deg; base += 32) {
            int n = min(32, deg - base);
            int eid = (lane < n) ? g_esrc[row + base + lane] : 0;
            for (int j = 0; j < n; j++) {
                int s = __shfl_sync(0xffffffffu, eid, j);
                float2 v = y2[s * 32 + lane];
                ax += v.x;
                ay += v.y;
            }
        }
        float inn = g_inn[node];
        float hx = fmaxf(fmaf(ax, inn, b1v.x), 0.f);
        float hy = fmaxf(fmaf(ay, inn, b1v.y), 0.f);
        float p = hx * w2v.x + hy * w2v.y;
#pragma unroll
        for (int o = 16; o; o >>= 1) p += __shfl_xor_sync(0xffffffffu, p, o);
        if (lane == 0) g_z[node] = p * g_outn[node];
    }
}

// ---------------------------------------------------------------- layer 2: scalar pull + sigmoid
__global__ void k_pull2(const float* __restrict__ b2, float* __restrict__ out, int nN) {
    int i = blockIdx.x * blockDim.x + threadIdx.x;
    if (i < nN) {
        int row = g_rowstart[i];
        int deg = g_degin[i];
        float s = 0.f;
        for (int e = 0; e < deg; e++) s += g_z[g_esrc[row + e]];
        out[i] = 1.f / (1.f + expf(-(s * g_inn[i] + b2[0])));
    }
}

// ---------------------------------------------------------------- launch
extern "C" void kernel_launch(void* const* d_in, const int* in_sizes, int n_in,
                              void* d_out, int out_size) {
    const float* feat = (const float*)d_in[0];
    const float* W1   = (const float*)d_in[1];
    const float* b1   = (const float*)d_in[2];
    const float* W2   = (const float*)d_in[3];
    const float* b2   = (const float*)d_in[4];
    const int*   src  = (const int*)d_in[5];
    const int*   dst  = (const int*)d_in[6];
    float* out = (float*)d_out;

    int nN = in_sizes[0] / D;
    int nE = in_sizes[5];

    const int B = 256;
    int gNode = (nN + B - 1) / B;
    int gEdge = (nE + B - 1) / B;
    int gWarp = (nN + (B / 32) - 1) / (B / 32);

    k_init <<<gNode, B>>>(nN);
    k_deg  <<<gEdge, B>>>(src, dst, nE);
    k_norm <<<gNode, B>>>(nN);
    k_csr  <<<gEdge, B>>>(src, dst, nE);
    k_gemm <<<gWarp, B>>>(feat, W1, nN);
    k_pull1<<<gWarp, B>>>(b1, W2, nN);
    k_pull2<<<gNode, B>>>(b2, out, nN);
}